// round 8
// baseline (speedup 1.0000x reference)
#include <cuda_runtime.h>
#include <math.h>
#include <stdint.h>

// DWCE loss — TMA (cp.async.bulk) smem-staged version.
// pred: [8,16,512,512] f32, target: [8,512,512] int32, out: scalar f32.
// Each block stages a 512-pixel tile (16 channel rows + target) into smem via
// bulk-async copies, then computes log-softmax + weighted sums from smem.

constexpr int C    = 16;
constexpr int NIMG = 8;
constexpr int HW   = 512 * 512;
constexpr int TPB  = 128;
constexpr int TILE = 512;                             // pixels per block
constexpr int PPT  = TILE / TPB;                      // 4 (float4)
constexpr int BLOCKS_PER_IMG = HW / TILE;             // 512
constexpr int GRID = NIMG * BLOCKS_PER_IMG;           // 4096
constexpr unsigned TILE_BYTES = (C + 1) * TILE * 4;   // 16 pred rows + target = 34816

__device__ float        g_S[NIMG * C];
__device__ float        g_cnt[NIMG * C];
__device__ unsigned int g_done;

__device__ __forceinline__ uint32_t smem_u32(const void* p) {
    return (uint32_t)__cvta_generic_to_shared(p);
}

__global__ void __launch_bounds__(TPB, 6) dwce_fused_kernel(
    const float* __restrict__ pred,
    const int* __restrict__ target,
    float* __restrict__ out)
{
    __shared__ __align__(16) float tile[C][TILE];   // 32 KB
    __shared__ __align__(16) int   tgt[TILE];       // 2 KB
    __shared__ __align__(8)  unsigned long long mbar;
    __shared__ float sS[C];
    __shared__ float sN[C];
    __shared__ float swcl[C];
    __shared__ float sratio[NIMG];
    __shared__ bool  is_last;

    const int tid  = threadIdx.x;
    const int lane = tid & 31;

    const int n   = blockIdx.x / BLOCKS_PER_IMG;
    const int blk = blockIdx.x % BLOCKS_PER_IMG;

    const uint32_t mb = smem_u32(&mbar);
    if (tid == 0) {
        asm volatile("mbarrier.init.shared.b64 [%0], %1;" :: "r"(mb), "r"(1) : "memory");
    }
    if (tid < C) { sS[tid] = 0.0f; sN[tid] = 0.0f; }
    __syncthreads();

    if (tid == 0) {
        asm volatile("mbarrier.arrive.expect_tx.shared.b64 _, [%0], %1;"
                     :: "r"(mb), "r"(TILE_BYTES) : "memory");
        const float* src_base = pred + (size_t)n * C * HW + (size_t)blk * TILE;
#pragma unroll
        for (int ch = 0; ch < C; ch++) {
            asm volatile(
                "cp.async.bulk.shared::cluster.global.mbarrier::complete_tx::bytes "
                "[%0], [%1], %2, [%3];"
                :: "r"(smem_u32(&tile[ch][0])),
                   "l"(src_base + (size_t)ch * HW),
                   "r"((unsigned)(TILE * 4)), "r"(mb) : "memory");
        }
        asm volatile(
            "cp.async.bulk.shared::cluster.global.mbarrier::complete_tx::bytes "
            "[%0], [%1], %2, [%3];"
            :: "r"(smem_u32(&tgt[0])),
               "l"(target + (size_t)n * HW + (size_t)blk * TILE),
               "r"((unsigned)(TILE * 4)), "r"(mb) : "memory");
    }

    // Wait for the full tile (parity 0; barrier used once per launch).
    {
        uint32_t done;
        do {
            asm volatile(
                "{\n\t.reg .pred p;\n\t"
                "mbarrier.try_wait.parity.acquire.cta.shared::cta.b64 p, [%1], %2, 0x989680;\n\t"
                "selp.b32 %0, 1, 0, p;\n\t}"
                : "=r"(done) : "r"(mb), "r"(0u) : "memory");
        } while (!done);
    }

    // ---- compute from smem ----
    const int4 tv = *reinterpret_cast<const int4*>(&tgt[tid * PPT]);
    const int t0 = tv.x & 15, t1 = tv.y & 15, t2 = tv.z & 15, t3 = tv.w & 15;

    // packed per-thread class counters: 16 classes x 8-bit in 4 u32
    unsigned int c0 = 0, c1 = 0, c2 = 0, c3 = 0;
    {
        const int ts[4] = {t0, t1, t2, t3};
#pragma unroll
        for (int i = 0; i < 4; i++) {
            const int t = ts[i];
            const unsigned int inc = 1u << ((t & 3) * 8);
            const int w = t >> 2;
            c0 += (w == 0) ? inc : 0u;
            c1 += (w == 1) ? inc : 0u;
            c2 += (w == 2) ? inc : 0u;
            c3 += (w == 3) ? inc : 0u;
        }
    }

    float4 s  = make_float4(0.f, 0.f, 0.f, 0.f);
    float4 vt = make_float4(0.f, 0.f, 0.f, 0.f);
#pragma unroll
    for (int ch = 0; ch < C; ch++) {
        const float4 v = *reinterpret_cast<const float4*>(&tile[ch][tid * PPT]);
        s.x += __expf(v.x);
        s.y += __expf(v.y);
        s.z += __expf(v.z);
        s.w += __expf(v.w);
        if (ch == t0) vt.x = v.x;
        if (ch == t1) vt.y = v.y;
        if (ch == t2) vt.z = v.z;
        if (ch == t3) vt.w = v.w;
    }

    const float lp0 = vt.x - __logf(s.x);
    const float lp1 = vt.y - __logf(s.y);
    const float lp2 = vt.z - __logf(s.z);
    const float lp3 = vt.w - __logf(s.w);

    atomicAdd(&sS[t0], lp0);
    atomicAdd(&sS[t1], lp1);
    atomicAdd(&sS[t2], lp2);
    atomicAdd(&sS[t3], lp3);

    const unsigned int r0 = __reduce_add_sync(0xffffffffu, c0);
    const unsigned int r1 = __reduce_add_sync(0xffffffffu, c1);
    const unsigned int r2 = __reduce_add_sync(0xffffffffu, c2);
    const unsigned int r3 = __reduce_add_sync(0xffffffffu, c3);
    if (lane < C) {
        const unsigned int rw = (lane < 4) ? r0 : (lane < 8) ? r1 : (lane < 12) ? r2 : r3;
        const unsigned int val = (rw >> ((lane & 3) * 8)) & 0xFFu;
        atomicAdd(&sN[lane], (float)val);
    }

    __syncthreads();
    if (tid < C) {
        atomicAdd(&g_S[n * C + tid],   sS[tid]);
        atomicAdd(&g_cnt[n * C + tid], sN[tid]);
    }

    // ---- last-block finalize ----
    __threadfence();
    if (tid == 0) {
        const unsigned int d = atomicAdd(&g_done, 1u);
        is_last = (d == (unsigned int)(GRID - 1));
    }
    __syncthreads();
    if (!is_last) return;

    if (tid < C) {
        float tot = 0.0f;
#pragma unroll
        for (int im = 0; im < NIMG; im++) tot += __ldcg(&g_cnt[im * C + tid]);
        swcl[tid] = (tot > 0.0f) ? (1.0f / (tot * (float)C)) : 0.0f;
    }
    __syncthreads();

    if (tid < NIMG) {
        float num = 0.0f, den = 0.0f;
#pragma unroll
        for (int cl = 0; cl < C; cl++) {
            const float w = swcl[cl];
            num += __ldcg(&g_S[tid * C + cl])   * w;
            den += __ldcg(&g_cnt[tid * C + cl]) * w;
        }
        sratio[tid] = num / den;
    }
    __syncthreads();

    if (tid == 0) {
        float acc = 0.0f;
#pragma unroll
        for (int im = 0; im < NIMG; im++) acc += sratio[im];
        out[0] = -acc / (float)NIMG;
        g_done = 0;
    }

    // Reset scratch for the next graph replay (128 entries each; TPB == 128).
    g_S[tid]   = 0.0f;
    g_cnt[tid] = 0.0f;
}

extern "C" void kernel_launch(void* const* d_in, const int* in_sizes, int n_in,
                              void* d_out, int out_size) {
    const float* pred   = (const float*)d_in[0];
    const int*   target = (const int*)d_in[1];
    float* out = (float*)d_out;

    dwce_fused_kernel<<<GRID, TPB>>>(pred, target, out);
}

// round 9
// speedup vs baseline: 1.3268x; 1.3268x over previous
#include <cuda_runtime.h>
#include <math.h>
#include <stdint.h>

// DWCE loss — persistent CTAs + 2-deep cp.async.bulk pipeline.
// pred: [8,16,512,512] f32, target: [8,512,512] int32, out: scalar f32.

constexpr int C    = 16;
constexpr int NIMG = 8;
constexpr int HW   = 512 * 512;
constexpr int TPB  = 128;
constexpr int TILE = 256;                       // pixels per tile
constexpr int PPT  = TILE / TPB;                // 2 (float2)
constexpr int TILES_PER_IMG = HW / TILE;        // 1024
constexpr int CTAS_PER_IMG  = 111;              // 8*111 = 888 = 6 CTAs x 148 SMs
constexpr int GRID = NIMG * CTAS_PER_IMG;       // 888 (single wave)
constexpr unsigned TILE_BYTES = (C + 1) * TILE * 4;   // 17408

__device__ float        g_S[NIMG * C];
__device__ float        g_cnt[NIMG * C];
__device__ unsigned int g_done;

__device__ __forceinline__ uint32_t smem_u32(const void* p) {
    return (uint32_t)__cvta_generic_to_shared(p);
}

__global__ void __launch_bounds__(TPB, 6) dwce_fused_kernel(
    const float* __restrict__ pred,
    const int* __restrict__ target,
    float* __restrict__ out)
{
    __shared__ __align__(16) float buf[2][C][TILE];   // 32 KB
    __shared__ __align__(16) int   tgtb[2][TILE];     // 2 KB
    __shared__ __align__(8)  unsigned long long mbar[2];
    __shared__ float sS[C];
    __shared__ float sN[C];
    __shared__ float swcl[C];
    __shared__ float sratio[NIMG];
    __shared__ bool  is_last;

    const int tid  = threadIdx.x;
    const int lane = tid & 31;
    const int n    = blockIdx.x / CTAS_PER_IMG;
    const int slot = blockIdx.x % CTAS_PER_IMG;

    const float* img_pred = pred   + (size_t)n * C * HW;
    const int*   img_tgt  = target + (size_t)n * HW;

    if (tid == 0) {
        asm volatile("mbarrier.init.shared.b64 [%0], %1;" :: "r"(smem_u32(&mbar[0])), "r"(1) : "memory");
        asm volatile("mbarrier.init.shared.b64 [%0], %1;" :: "r"(smem_u32(&mbar[1])), "r"(1) : "memory");
    }
    if (tid < C) { sS[tid] = 0.0f; sN[tid] = 0.0f; }
    __syncthreads();

    // thread-0 tile fetch into stage s
    auto fetch = [&](int t, int s) {
        const uint32_t mb = smem_u32(&mbar[s]);
        asm volatile("mbarrier.arrive.expect_tx.shared.b64 _, [%0], %1;"
                     :: "r"(mb), "r"(TILE_BYTES) : "memory");
#pragma unroll
        for (int ch = 0; ch < C; ch++) {
            asm volatile(
                "cp.async.bulk.shared::cluster.global.mbarrier::complete_tx::bytes "
                "[%0], [%1], %2, [%3];"
                :: "r"(smem_u32(&buf[s][ch][0])),
                   "l"(img_pred + (size_t)ch * HW + (size_t)t * TILE),
                   "r"((unsigned)(TILE * 4)), "r"(mb) : "memory");
        }
        asm volatile(
            "cp.async.bulk.shared::cluster.global.mbarrier::complete_tx::bytes "
            "[%0], [%1], %2, [%3];"
            :: "r"(smem_u32(&tgtb[s][0])),
               "l"(img_tgt + (size_t)t * TILE),
               "r"((unsigned)(TILE * 4)), "r"(mb) : "memory");
    };

    if (tid == 0 && slot < TILES_PER_IMG) fetch(slot, 0);

    // per-thread packed class counters (16 classes x 8-bit in 4 u32),
    // accumulated across ALL tiles of this CTA (max 20 per field).
    unsigned int c0 = 0, c1 = 0, c2 = 0, c3 = 0;

    int iter = 0;
    for (int t = slot; t < TILES_PER_IMG; t += CTAS_PER_IMG, iter++) {
        const int s = iter & 1;
        const int tn = t + CTAS_PER_IMG;
        if (tid == 0 && tn < TILES_PER_IMG) fetch(tn, s ^ 1);

        // wait stage s, parity = (use count)&1 = (iter>>1)&1
        {
            const uint32_t mb = smem_u32(&mbar[s]);
            const uint32_t par = (iter >> 1) & 1;
            uint32_t done;
            do {
                asm volatile(
                    "{\n\t.reg .pred p;\n\t"
                    "mbarrier.try_wait.parity.acquire.cta.shared::cta.b64 p, [%1], %2, 0x989680;\n\t"
                    "selp.b32 %0, 1, 0, p;\n\t}"
                    : "=r"(done) : "r"(mb), "r"(par) : "memory");
            } while (!done);
        }

        const int2 tv = *reinterpret_cast<const int2*>(&tgtb[s][tid * PPT]);
        const int t0 = tv.x & 15, t1 = tv.y & 15;

        {
            const unsigned int inc0 = 1u << ((t0 & 3) * 8);
            const int w0 = t0 >> 2;
            c0 += (w0 == 0) ? inc0 : 0u;  c1 += (w0 == 1) ? inc0 : 0u;
            c2 += (w0 == 2) ? inc0 : 0u;  c3 += (w0 == 3) ? inc0 : 0u;
            const unsigned int inc1 = 1u << ((t1 & 3) * 8);
            const int w1 = t1 >> 2;
            c0 += (w1 == 0) ? inc1 : 0u;  c1 += (w1 == 1) ? inc1 : 0u;
            c2 += (w1 == 2) ? inc1 : 0u;  c3 += (w1 == 3) ? inc1 : 0u;
        }

        float sx = 0.f, sy = 0.f, vtx = 0.f, vty = 0.f;
#pragma unroll
        for (int ch = 0; ch < C; ch++) {
            const float2 v = *reinterpret_cast<const float2*>(&buf[s][ch][tid * PPT]);
            sx += __expf(v.x);
            sy += __expf(v.y);
            if (ch == t0) vtx = v.x;
            if (ch == t1) vty = v.y;
        }

        atomicAdd(&sS[t0], vtx - __logf(sx));
        atomicAdd(&sS[t1], vty - __logf(sy));

        __syncthreads();   // compute done before this buffer is refetched
    }

    // fold packed counters: warp REDUX, one 16-lane shared atomic per warp
    const unsigned int r0 = __reduce_add_sync(0xffffffffu, c0);
    const unsigned int r1 = __reduce_add_sync(0xffffffffu, c1);
    const unsigned int r2 = __reduce_add_sync(0xffffffffu, c2);
    const unsigned int r3 = __reduce_add_sync(0xffffffffu, c3);
    if (lane < C) {
        const unsigned int rw = (lane < 4) ? r0 : (lane < 8) ? r1 : (lane < 12) ? r2 : r3;
        atomicAdd(&sN[lane], (float)((rw >> ((lane & 3) * 8)) & 0xFFu));
    }
    __syncthreads();

    if (tid < C) {
        atomicAdd(&g_S[n * C + tid],   sS[tid]);
        atomicAdd(&g_cnt[n * C + tid], sN[tid]);
    }

    // ---- last-block finalize ----
    __threadfence();
    if (tid == 0) {
        const unsigned int d = atomicAdd(&g_done, 1u);
        is_last = (d == (unsigned int)(GRID - 1));
    }
    __syncthreads();
    if (!is_last) return;

    if (tid < C) {
        float tot = 0.0f;
#pragma unroll
        for (int im = 0; im < NIMG; im++) tot += __ldcg(&g_cnt[im * C + tid]);
        swcl[tid] = (tot > 0.0f) ? (1.0f / (tot * (float)C)) : 0.0f;
    }
    __syncthreads();

    if (tid < NIMG) {
        float num = 0.0f, den = 0.0f;
#pragma unroll
        for (int cl = 0; cl < C; cl++) {
            const float w = swcl[cl];
            num += __ldcg(&g_S[tid * C + cl])   * w;
            den += __ldcg(&g_cnt[tid * C + cl]) * w;
        }
        sratio[tid] = num / den;
    }
    __syncthreads();

    if (tid == 0) {
        float acc = 0.0f;
#pragma unroll
        for (int im = 0; im < NIMG; im++) acc += sratio[im];
        out[0] = -acc / (float)NIMG;
        g_done = 0;
    }

    // Reset scratch for the next graph replay (TPB == 128 == NIMG*C).
    g_S[tid]   = 0.0f;
    g_cnt[tid] = 0.0f;
}

extern "C" void kernel_launch(void* const* d_in, const int* in_sizes, int n_in,
                              void* d_out, int out_size) {
    const float* pred   = (const float*)d_in[0];
    const int*   target = (const int*)d_in[1];
    float* out = (float*)d_out;

    dwce_fused_kernel<<<GRID, TPB>>>(pred, target, out);
}